// round 9
// baseline (speedup 1.0000x reference)
#include <cuda_runtime.h>

#define Wn 262144
#define Ln 32
#define Nn (Ln * Wn)
#define CAP 2048   // spawned-sibling queue (nonterminals only); expected ~16 total

// Linear DAG cone evaluation, single warp.
// root = sum over path-tree leaves of (prod path weights) * values[leaf] * w_term.
// Active lanes follow one nonterminal child in registers (chain = LDG -> LDG);
// terminal children fold into acc at fork; a second nonterminal child is
// queued via ballot prefix-sum and claimed by idle lanes.
__global__ void __launch_bounds__(32) cone_kernel(
    const float* __restrict__ values,
    const int2*  __restrict__ idx2,     // child_idx as [L-1,W] int2
    const int*   __restrict__ types,    // node_types [L-1,W]
    const float* __restrict__ w_term,
    const float* __restrict__ w_plus,
    const float* __restrict__ w_minus,
    const float* __restrict__ w_final,
    const float* __restrict__ b_final,
    float* __restrict__ out)
{
    __shared__ int2 s_q[CAP];           // (node id, coef bits), both-nonterminal spawns

    const int lane = threadIdx.x;
    const unsigned below = (1u << lane) - 1u;
    const unsigned FULL = 0xFFFFFFFFu;
    const float2 P = *(const float2*)w_plus;
    const float2 M = *(const float2*)w_minus;

    float acc = 0.0f;
    int head = 0, tail = 0;             // warp-uniform cursors, no atomics

    bool  active = (lane == 0);
    int   v = Nn - 1;                   // root lives in lane 0's registers
    float c = 1.0f;

    for (int iter = 0; iter < 96; iter++) {
        bool spawn = false;
        int   sv = 0;
        float sc = 0.0f;

        if (active) {
            int base = v - Wn;                   // v is guaranteed nonterminal
            int2 ch = __ldg(&idx2[base]);        // the dependent gather
            int  t  = __ldg(&types[base]);       // overlapped
            float c0 = c * ((t == 1) ? P.x : M.x);
            float c1 = c * ((t == 1) ? P.y : M.y);

            bool xt = (ch.x < Wn), yt = (ch.y < Wn);
            if (xt) acc += c0 * __ldg(&values[ch.x]);   // terminal inline
            if (yt) acc += c1 * __ldg(&values[ch.y]);

            if (!xt) {                            // follow x in registers
                v = ch.x; c = c0;
                if (!yt) { spawn = true; sv = ch.y; sc = c1; }
            } else if (!yt) {                     // follow y in registers
                v = ch.y; c = c1;
            } else {
                active = false;                   // both terminal: lane done
            }
        }

        // Queue spawned siblings (<=1 per lane) via ballot prefix-sum
        unsigned S = __ballot_sync(FULL, spawn);
        if (spawn) {
            int p = tail + __popc(S & below);
            if (p < CAP) s_q[p] = make_int2(sv, __float_as_int(sc));
        }
        tail = min(tail + __popc(S), CAP);
        __syncwarp();                             // spawn writes visible

        // Idle lanes claim queued work (warp-synchronous, no atomics)
        unsigned idle = __ballot_sync(FULL, !active);
        int avail = tail - head;
        if (!active) {
            int rank = __popc(idle & below);
            if (rank < avail) {
                int2 e = s_q[head + rank];
                v = e.x;
                c = __int_as_float(e.y);
                active = true;
            }
        }
        head += min(avail, __popc(idle));

        if (__ballot_sync(FULL, active) == 0) break;   // nothing left anywhere
    }

    // Warp reduction
    #pragma unroll
    for (int s = 16; s > 0; s >>= 1)
        acc += __shfl_xor_sync(FULL, acc, s);

    if (lane == 0) {
        float root = acc * __ldg(w_term);
        out[0] = fmaf(root, __ldg(w_final), __ldg(b_final));
    }
}

extern "C" void kernel_launch(void* const* d_in, const int* in_sizes, int n_in,
                              void* d_out, int out_size) {
    const float* values     = (const float*)d_in[0];
    const int*   child_idx  = (const int*)d_in[1];   // [L-1, W, 2]
    const int*   node_types = (const int*)d_in[2];   // [L-1, W]
    const float* w_term     = (const float*)d_in[3];
    const float* w_plus     = (const float*)d_in[4];
    const float* w_minus    = (const float*)d_in[5];
    const float* w_final    = (const float*)d_in[6];
    const float* b_final    = (const float*)d_in[7];
    float* out = (float*)d_out;

    cone_kernel<<<1, 32>>>(values,
                           (const int2*)child_idx,
                           node_types,
                           w_term, w_plus, w_minus, w_final, b_final,
                           out);
}

// round 10
// speedup vs baseline: 1.0037x; 1.0037x over previous
#include <cuda_runtime.h>

#define Wn 262144
#define Ln 32
#define Nn (Ln * Wn)
#define CAP 2048   // spawned-sibling queue (nonterminals only); expected ~16 total

// Linear DAG cone evaluation, single warp.
// root = sum over path-tree leaves of (prod path weights) * values[leaf] * w_term.
// Active lanes follow one nonterminal child in registers (chain = LDG -> LDG);
// terminal children fold into acc at fork; a second nonterminal child is
// queued via ballot prefix-sum and claimed by idle lanes. Two ballots/iter.
__global__ void __launch_bounds__(32) cone_kernel(
    const float* __restrict__ values,
    const int2*  __restrict__ idx2,     // child_idx as [L-1,W] int2
    const int*   __restrict__ types,    // node_types [L-1,W]
    const float* __restrict__ w_term,
    const float* __restrict__ w_plus,
    const float* __restrict__ w_minus,
    const float* __restrict__ w_final,
    const float* __restrict__ b_final,
    float* __restrict__ out)
{
    __shared__ int2 s_q[CAP];           // (node id, coef bits)

    const int lane = threadIdx.x;
    const unsigned below = (1u << lane) - 1u;
    const unsigned FULL = 0xFFFFFFFFu;
    const float2 P = *(const float2*)w_plus;
    const float2 M = *(const float2*)w_minus;

    float acc = 0.0f;
    int head = 0, tail = 0;             // warp-uniform cursors, no atomics

    bool  active = (lane == 0);
    int   v = Nn - 1;                   // root in lane 0's registers
    float c = 1.0f;

    for (int iter = 0; iter < 96; iter++) {
        bool spawn = false;
        int   sv = 0;
        float sc = 0.0f;

        if (active) {
            int base = v - Wn;                   // v guaranteed nonterminal
            int2 ch = __ldg(&idx2[base]);        // the dependent gather
            int  t  = __ldg(&types[base]);       // overlapped, off critical path
            float c0 = c * ((t == 1) ? P.x : M.x);
            float c1 = c * ((t == 1) ? P.y : M.y);

            bool xt = (ch.x < Wn), yt = (ch.y < Wn);
            if (xt) acc += c0 * __ldg(&values[ch.x]);   // terminal inline
            if (yt) acc += c1 * __ldg(&values[ch.y]);

            if (!xt) {                            // follow x in registers
                v = ch.x; c = c0;
                if (!yt) { spawn = true; sv = ch.y; sc = c1; }
            } else if (!yt) {                     // follow y in registers
                v = ch.y; c = c1;
            } else {
                active = false;                   // both terminal: lane done
            }
        }

        // Ballot 1: queue spawned siblings (<=1 per lane), prefix by ballot rank
        unsigned S = __ballot_sync(FULL, spawn);
        if (spawn) {
            int p = tail + __popc(S & below);
            if (p < CAP) s_q[p] = make_int2(sv, __float_as_int(sc));
        }
        if (S) {
            tail = min(tail + __popc(S), CAP);
            __syncwarp();                         // spawn writes visible
        }

        // Ballot 2: idle lanes claim queued work; doubles as exit test
        unsigned idle = __ballot_sync(FULL, !active);
        int avail = tail - head;
        if (idle == FULL && avail == 0) break;    // nothing running, nothing queued
        if (avail > 0) {
            if (!active) {
                int rank = __popc(idle & below);
                if (rank < avail) {
                    int2 e = s_q[head + rank];
                    v = e.x;
                    c = __int_as_float(e.y);
                    active = true;
                }
            }
            int nidle = __popc(idle);
            head += (avail < nidle) ? avail : nidle;
        }
    }

    // Warp reduction
    #pragma unroll
    for (int s = 16; s > 0; s >>= 1)
        acc += __shfl_xor_sync(FULL, acc, s);

    if (lane == 0) {
        float root = acc * __ldg(w_term);
        out[0] = fmaf(root, __ldg(w_final), __ldg(b_final));
    }
}

extern "C" void kernel_launch(void* const* d_in, const int* in_sizes, int n_in,
                              void* d_out, int out_size) {
    const float* values     = (const float*)d_in[0];
    const int*   child_idx  = (const int*)d_in[1];   // [L-1, W, 2]
    const int*   node_types = (const int*)d_in[2];   // [L-1, W]
    const float* w_term     = (const float*)d_in[3];
    const float* w_plus     = (const float*)d_in[4];
    const float* w_minus    = (const float*)d_in[5];
    const float* w_final    = (const float*)d_in[6];
    const float* b_final    = (const float*)d_in[7];
    float* out = (float*)d_out;

    cone_kernel<<<1, 32>>>(values,
                           (const int2*)child_idx,
                           node_types,
                           w_term, w_plus, w_minus, w_final, b_final,
                           out);
}